// round 10
// baseline (speedup 1.0000x reference)
#include <cuda_runtime.h>
#include <cuda_bf16.h>
#include <math.h>

#define Nn    20000
#define Ee    320000
#define FIN   256
#define HIDD  32
#define HEADS 8
#define EDIM  8
#define NEG   0.2f

// ---------------- scratch (device globals; no allocation allowed) ----------
__device__ float g_M1[EDIM * HEADS];        // M1[d*8+h]
__device__ float g_M2[EDIM];
__device__ float g_esum[(size_t)Nn * EDIM];
__device__ int   g_deg[Nn];
__device__ int   g_rowoff[Nn + 1];
__device__ int   g_cursor[Nn];
__device__ float g_aedge1[(size_t)Ee * HEADS];   // per-edge, [E][8]
__device__ float g_aedge2[Ee];
__device__ int   g_csr_src[Ee];
__device__ float g_csr_ae1[(size_t)HEADS * Ee];  // head-major over csr slots
__device__ float g_csr_ae2[Ee];
__device__ float g_h1[(size_t)Nn * 256];
__device__ float g_hmid[(size_t)Nn * 256];
__device__ float g_h2[(size_t)Nn * HIDD];
__device__ float g_asrc1[(size_t)Nn * HEADS];
__device__ float g_adst1[(size_t)Nn * HEADS];
__device__ float g_aloop1[(size_t)Nn * HEADS];
__device__ float g_asrc2[Nn];
__device__ float g_adst2[Nn];
__device__ float g_aloop2[Nn];

// ---------------- helpers ----------------
__device__ __forceinline__ float lrelu(float x) { return x > 0.f ? x : NEG * x; }
__device__ __forceinline__ float wredSum(float v) {
    #pragma unroll
    for (int o = 16; o > 0; o >>= 1) v += __shfl_xor_sync(0xffffffffu, v, o);
    return v;
}
__device__ __forceinline__ float wredMax(float v) {
    #pragma unroll
    for (int o = 16; o > 0; o >>= 1) v = fmaxf(v, __shfl_xor_sync(0xffffffffu, v, o));
    return v;
}

// ---------------- K0: zero deg + esum ----------------
__global__ void k_init() {
    int i = blockIdx.x * blockDim.x + threadIdx.x;
    if (i < Nn * EDIM) g_esum[i] = 0.f;
    if (i < Nn)        g_deg[i]  = 0;
}

// ---------------- K_pre: fold attention vectors into edge projections ------
__global__ void k_pre(const float* __restrict__ We1, const float* __restrict__ ae1,
                      const float* __restrict__ We2, const float* __restrict__ ae2) {
    int t = threadIdx.x;
    if (t < 64) {
        int d = t / 8, h = t % 8;
        float s = 0.f;
        #pragma unroll
        for (int c = 0; c < 32; c++) s += We1[d * 256 + h * 32 + c] * ae1[h * 32 + c];
        g_M1[d * 8 + h] = s;
    }
    if (t < 8) {
        float s = 0.f;
        #pragma unroll
        for (int c = 0; c < 32; c++) s += We2[t * 32 + c] * ae2[c];
        g_M2[t] = s;
    }
}

// ---------------- K1: edge embed + deg/esum + a_edge for both convs --------
__global__ void k_edge(const int* __restrict__ ei, const float* __restrict__ ea,
                       const float* __restrict__ Wse, const float* __restrict__ bse) {
    int e = blockIdx.x * blockDim.x + threadIdx.x;
    if (e >= Ee) return;
    int d = ei[Ee + e];          // dst row
    float a0 = ea[2 * e], a1 = ea[2 * e + 1];
    float v[8];
    #pragma unroll
    for (int j = 0; j < 8; j++) {
        float t = a0 * __ldg(&Wse[j]) + a1 * __ldg(&Wse[8 + j]) + __ldg(&bse[j]);
        v[j] = fmaxf(t, 0.f);
        atomicAdd(&g_esum[(size_t)d * 8 + j], v[j]);
    }
    atomicAdd(&g_deg[d], 1);
    #pragma unroll
    for (int h = 0; h < 8; h++) {
        float s = 0.f;
        #pragma unroll
        for (int dd = 0; dd < 8; dd++) s += v[dd] * g_M1[dd * 8 + h];
        g_aedge1[(size_t)e * 8 + h] = s;
    }
    float s2 = 0.f;
    #pragma unroll
    for (int dd = 0; dd < 8; dd++) s2 += v[dd] * g_M2[dd];
    g_aedge2[e] = s2;
}

// ---------------- K2a: single-block exclusive scan of deg -> rowoff --------
__global__ void k_scan() {
    __shared__ int partial[1024];
    int t = threadIdx.x;
    const int CH = (Nn + 1023) / 1024;            // 20
    int s = t * CH;
    int e = min(s + CH, Nn);
    int local = 0;
    for (int i = s; i < e; i++) local += g_deg[i];
    partial[t] = local;
    __syncthreads();
    for (int off = 1; off < 1024; off <<= 1) {
        int v = 0;
        if (t >= off) v = partial[t - off];
        __syncthreads();
        if (t >= off) partial[t] += v;
        __syncthreads();
    }
    int run = (t > 0) ? partial[t - 1] : 0;
    for (int i = s; i < e; i++) {
        g_rowoff[i] = run;
        g_cursor[i] = run;
        run += g_deg[i];
    }
    if (t == 1023) g_rowoff[Nn] = partial[1023];
}

// ---------------- K2b: e_mean -> self-loop attention terms -----------------
__global__ void k_mean() {
    int n = blockIdx.x * blockDim.x + threadIdx.x;
    if (n >= Nn) return;
    float inv = 1.f / fmaxf((float)g_deg[n], 1.f);
    float em[8];
    #pragma unroll
    for (int d = 0; d < 8; d++) em[d] = g_esum[(size_t)n * 8 + d] * inv;
    #pragma unroll
    for (int h = 0; h < 8; h++) {
        float s = 0.f;
        #pragma unroll
        for (int d = 0; d < 8; d++) s += em[d] * g_M1[d * 8 + h];
        g_aloop1[(size_t)n * 8 + h] = s;
    }
    float s2 = 0.f;
    #pragma unroll
    for (int d = 0; d < 8; d++) s2 += em[d] * g_M2[d];
    g_aloop2[n] = s2;
}

// ---------------- K3: CSR fill ----------------
__global__ void k_fill(const int* __restrict__ ei) {
    int e = blockIdx.x * blockDim.x + threadIdx.x;
    if (e >= Ee) return;
    int d = ei[Ee + e];
    int pos = atomicAdd(&g_cursor[d], 1);
    g_csr_src[pos] = ei[e];
    #pragma unroll
    for (int h = 0; h < 8; h++)
        g_csr_ae1[(size_t)h * Ee + pos] = g_aedge1[(size_t)e * 8 + h];
    g_csr_ae2[pos] = g_aedge2[e];
}

// ---------------- K4: GEMM1 h1 = x @ W1 (20000x256 @ 256x256) --------------
#define BM 64
#define BN 64
#define BK 16
__global__ void k_gemm1(const float* __restrict__ X, const float* __restrict__ W) {
    __shared__ float As[BK][BM + 1];
    __shared__ float Bs[BK][BN];
    int tid = threadIdx.x;                 // 256 threads = 16x16
    int tx = tid % 16, ty = tid / 16;
    int brow = blockIdx.x * BM;
    int bcol = blockIdx.y * BN;
    float acc[4][4];
    #pragma unroll
    for (int i = 0; i < 4; i++)
        #pragma unroll
        for (int j = 0; j < 4; j++) acc[i][j] = 0.f;

    for (int k0 = 0; k0 < 256; k0 += BK) {
        #pragma unroll
        for (int i = tid; i < BM * BK; i += 256) {
            int r = i / BK, c = i % BK;
            int gr = brow + r;
            As[c][r] = (gr < Nn) ? X[(size_t)gr * 256 + k0 + c] : 0.f;
        }
        #pragma unroll
        for (int i = tid; i < BK * BN; i += 256) {
            int r = i / BN, c = i % BN;
            Bs[r][c] = W[(size_t)(k0 + r) * 256 + bcol + c];
        }
        __syncthreads();
        #pragma unroll
        for (int kk = 0; kk < BK; kk++) {
            float a[4], b[4];
            #pragma unroll
            for (int i = 0; i < 4; i++) a[i] = As[kk][ty * 4 + i];
            #pragma unroll
            for (int j = 0; j < 4; j++) b[j] = Bs[kk][tx * 4 + j];
            #pragma unroll
            for (int i = 0; i < 4; i++)
                #pragma unroll
                for (int j = 0; j < 4; j++) acc[i][j] += a[i] * b[j];
        }
        __syncthreads();
    }
    #pragma unroll
    for (int i = 0; i < 4; i++) {
        int gr = brow + ty * 4 + i;
        if (gr < Nn) {
            #pragma unroll
            for (int j = 0; j < 4; j++)
                g_h1[(size_t)gr * 256 + bcol + tx * 4 + j] = acc[i][j];
        }
    }
}

// ---------------- K5: per-node attention scalars for conv1 -----------------
__global__ void k_attn1(const float* __restrict__ as1, const float* __restrict__ ad1) {
    int warp = threadIdx.x / 32, lane = threadIdx.x % 32;
    int n = blockIdx.x * 8 + warp;
    if (n >= Nn) return;
    #pragma unroll
    for (int h = 0; h < 8; h++) {
        float val = g_h1[(size_t)n * 256 + h * 32 + lane];
        float s = wredSum(val * __ldg(&as1[h * 32 + lane]));
        float d = wredSum(val * __ldg(&ad1[h * 32 + lane]));
        if (lane == 0) { g_asrc1[(size_t)n * 8 + h] = s; g_adst1[(size_t)n * 8 + h] = d; }
    }
}

// ---------------- K6: conv1 softmax + aggregate (1 block/node, warp/head) --
__global__ void k_conv1(const float* __restrict__ b1) {
    int n = blockIdx.x;
    int h = threadIdx.x / 32, lane = threadIdx.x % 32;
    int beg = g_rowoff[n], end = g_rowoff[n + 1];
    float adst = g_adst1[(size_t)n * 8 + h];
    float self_raw = lrelu(g_asrc1[(size_t)n * 8 + h] + adst + g_aloop1[(size_t)n * 8 + h]);
    const float* ae = g_csr_ae1 + (size_t)h * Ee;

    float m = self_raw;
    for (int j = beg + lane; j < end; j += 32) {
        int s = g_csr_src[j];
        m = fmaxf(m, lrelu(g_asrc1[(size_t)s * 8 + h] + adst + ae[j]));
    }
    m = wredMax(m);

    float ssum = 0.f;
    for (int j = beg + lane; j < end; j += 32) {
        int s = g_csr_src[j];
        ssum += expf(lrelu(g_asrc1[(size_t)s * 8 + h] + adst + ae[j]) - m);
    }
    ssum = wredSum(ssum) + expf(self_raw - m);
    float inv = 1.f / (ssum + 1e-16f);

    float acc = expf(self_raw - m) * inv * g_h1[(size_t)n * 256 + h * 32 + lane];
    for (int base = beg; base < end; base += 32) {
        int j = base + lane;
        float al = 0.f; int s = 0;
        if (j < end) {
            s = g_csr_src[j];
            al = expf(lrelu(g_asrc1[(size_t)s * 8 + h] + adst + ae[j]) - m) * inv;
        }
        int cnt = min(32, end - base);
        for (int i = 0; i < cnt; i++) {
            float a = __shfl_sync(0xffffffffu, al, i);
            int ss = __shfl_sync(0xffffffffu, s, i);
            acc += a * g_h1[(size_t)ss * 256 + h * 32 + lane];
        }
    }
    float v = acc + __ldg(&b1[h * 32 + lane]);
    g_hmid[(size_t)n * 256 + h * 32 + lane] = fmaxf(v, 0.f);   // bias + relu
}

// ---------------- K7: GEMM2 h2 = hmid @ W2 + fused attn scalars ------------
__global__ void k_gemm2(const float* __restrict__ W2, const float* __restrict__ as2,
                        const float* __restrict__ ad2) {
    __shared__ float Ws[256 * 32];
    __shared__ float Xs[8 * 256];
    int tid = threadIdx.x;
    for (int i = tid; i < 256 * 32; i += 256) Ws[i] = W2[i];
    int row0 = blockIdx.x * 8;
    for (int i = tid; i < 8 * 256; i += 256) {
        int r = row0 + i / 256;
        Xs[i] = (r < Nn) ? g_hmid[(size_t)r * 256 + (i % 256)] : 0.f;
    }
    __syncthreads();
    int r = tid / 32, c = tid % 32;
    int n = row0 + r;
    float acc = 0.f;
    #pragma unroll 8
    for (int k = 0; k < 256; k++) acc += Xs[r * 256 + k] * Ws[k * 32 + c];
    if (n < Nn) {
        g_h2[(size_t)n * 32 + c] = acc;
        float s1 = wredSum(acc * __ldg(&as2[c]));
        float s2 = wredSum(acc * __ldg(&ad2[c]));
        if (c == 0) { g_asrc2[n] = s1; g_adst2[n] = s2; }
    }
}

// ---------------- K8: conv2 softmax + aggregate (warp per node) ------------
__global__ void k_conv2(const float* __restrict__ b2, float* __restrict__ out) {
    int warp = threadIdx.x / 32, lane = threadIdx.x % 32;
    int n = blockIdx.x * 8 + warp;
    if (n >= Nn) return;
    int beg = g_rowoff[n], end = g_rowoff[n + 1];
    float adst = g_adst2[n];
    float self_raw = lrelu(g_asrc2[n] + adst + g_aloop2[n]);

    float m = self_raw;
    for (int j = beg + lane; j < end; j += 32)
        m = fmaxf(m, lrelu(g_asrc2[g_csr_src[j]] + adst + g_csr_ae2[j]));
    m = wredMax(m);

    float ssum = 0.f;
    for (int j = beg + lane; j < end; j += 32)
        ssum += expf(lrelu(g_asrc2[g_csr_src[j]] + adst + g_csr_ae2[j]) - m);
    ssum = wredSum(ssum) + expf(self_raw - m);
    float inv = 1.f / (ssum + 1e-16f);

    float acc = expf(self_raw - m) * inv * g_h2[(size_t)n * 32 + lane];
    for (int base = beg; base < end; base += 32) {
        int j = base + lane;
        float al = 0.f; int s = 0;
        if (j < end) {
            s = g_csr_src[j];
            al = expf(lrelu(g_asrc2[s] + adst + g_csr_ae2[j]) - m) * inv;
        }
        int cnt = min(32, end - base);
        for (int i = 0; i < cnt; i++) {
            float a = __shfl_sync(0xffffffffu, al, i);
            int ss = __shfl_sync(0xffffffffu, s, i);
            acc += a * g_h2[(size_t)ss * 32 + lane];
        }
    }
    out[(size_t)n * 32 + lane] = acc + __ldg(&b2[lane]);
}

// ---------------- launcher ----------------
extern "C" void kernel_launch(void* const* d_in, const int* in_sizes, int n_in,
                              void* d_out, int out_size) {
    const float* x   = (const float*)d_in[0];
    const int*   ei  = (const int*)  d_in[1];
    const float* ea  = (const float*)d_in[2];
    const float* Wse = (const float*)d_in[3];
    const float* bse = (const float*)d_in[4];
    const float* W1  = (const float*)d_in[5];
    const float* as1 = (const float*)d_in[6];
    const float* ad1 = (const float*)d_in[7];
    const float* We1 = (const float*)d_in[8];
    const float* ae1 = (const float*)d_in[9];
    const float* b1  = (const float*)d_in[10];
    const float* W2  = (const float*)d_in[11];
    const float* as2 = (const float*)d_in[12];
    const float* ad2 = (const float*)d_in[13];
    const float* We2 = (const float*)d_in[14];
    const float* ae2 = (const float*)d_in[15];
    const float* b2  = (const float*)d_in[16];
    float* out = (float*)d_out;

    k_init<<<(Nn * EDIM + 255) / 256, 256>>>();
    k_pre<<<1, 64>>>(We1, ae1, We2, ae2);
    k_edge<<<(Ee + 255) / 256, 256>>>(ei, ea, Wse, bse);
    k_scan<<<1, 1024>>>();
    k_mean<<<(Nn + 255) / 256, 256>>>();
    k_fill<<<(Ee + 255) / 256, 256>>>(ei);
    dim3 g1((Nn + BM - 1) / BM, 256 / BN);
    k_gemm1<<<g1, 256>>>(x, W1);
    k_attn1<<<(Nn + 7) / 8, 256>>>(as1, ad1);
    k_conv1<<<Nn, 256>>>(b1);
    k_gemm2<<<(Nn + 7) / 8, 256>>>(W2, as2, ad2);
    k_conv2<<<(Nn + 7) / 8, 256>>>(b2, out);
}

// round 11
// speedup vs baseline: 1.0067x; 1.0067x over previous
#include <cuda_runtime.h>
#include <cuda_bf16.h>
#include <math.h>

#define Nn    20000
#define Ee    320000
#define FIN   256
#define HIDD  32
#define HEADS 8
#define EDIM  8
#define NEG   0.2f

// ---------------- scratch (device globals; no allocation allowed) ----------
__device__ float g_M1[EDIM * HEADS];        // M1[d*8+h]
__device__ float g_M2[EDIM];
__device__ float g_esum[(size_t)Nn * EDIM];
__device__ int   g_deg[Nn];
__device__ int   g_rowoff[Nn + 1];
__device__ int   g_cursor[Nn];
__device__ float g_aedge1[(size_t)Ee * HEADS];   // per-edge, [E][8]
__device__ float g_aedge2[Ee];
__device__ int   g_csr_src[Ee];
__device__ float g_csr_ae1[(size_t)HEADS * Ee];  // head-major over csr slots
__device__ float g_csr_ae2[Ee];
__device__ float g_h1[(size_t)Nn * 256];
__device__ float g_hmid[(size_t)Nn * 256];
__device__ float g_h2[(size_t)Nn * HIDD];
__device__ float g_asrc1[(size_t)Nn * HEADS];
__device__ float g_adst1[(size_t)Nn * HEADS];
__device__ float g_aloop1[(size_t)Nn * HEADS];
__device__ float g_asrc2[Nn];
__device__ float g_adst2[Nn];
__device__ float g_aloop2[Nn];

// ---------------- helpers ----------------
__device__ __forceinline__ float lrelu(float x) { return x > 0.f ? x : NEG * x; }
__device__ __forceinline__ float wredSum(float v) {
    #pragma unroll
    for (int o = 16; o > 0; o >>= 1) v += __shfl_xor_sync(0xffffffffu, v, o);
    return v;
}
__device__ __forceinline__ float wredMax(float v) {
    #pragma unroll
    for (int o = 16; o > 0; o >>= 1) v = fmaxf(v, __shfl_xor_sync(0xffffffffu, v, o));
    return v;
}

// ---------------- K0: zero deg + esum ----------------
__global__ void k_init() {
    int i = blockIdx.x * blockDim.x + threadIdx.x;
    if (i < Nn * EDIM) g_esum[i] = 0.f;
    if (i < Nn)        g_deg[i]  = 0;
}

// ---------------- K_pre: fold attention vectors into edge projections ------
__global__ void k_pre(const float* __restrict__ We1, const float* __restrict__ ae1,
                      const float* __restrict__ We2, const float* __restrict__ ae2) {
    int t = threadIdx.x;
    if (t < 64) {
        int d = t / 8, h = t % 8;
        float s = 0.f;
        #pragma unroll
        for (int c = 0; c < 32; c++) s += We1[d * 256 + h * 32 + c] * ae1[h * 32 + c];
        g_M1[d * 8 + h] = s;
    }
    if (t < 8) {
        float s = 0.f;
        #pragma unroll
        for (int c = 0; c < 32; c++) s += We2[t * 32 + c] * ae2[c];
        g_M2[t] = s;
    }
}

// ---------------- K1: edge embed + deg/esum + a_edge for both convs --------
__global__ void k_edge(const int* __restrict__ ei, const float* __restrict__ ea,
                       const float* __restrict__ Wse, const float* __restrict__ bse) {
    int e = blockIdx.x * blockDim.x + threadIdx.x;
    if (e >= Ee) return;
    int d = ei[Ee + e];          // dst row
    float a0 = ea[2 * e], a1 = ea[2 * e + 1];
    float v[8];
    #pragma unroll
    for (int j = 0; j < 8; j++) {
        float t = a0 * __ldg(&Wse[j]) + a1 * __ldg(&Wse[8 + j]) + __ldg(&bse[j]);
        v[j] = fmaxf(t, 0.f);
        atomicAdd(&g_esum[(size_t)d * 8 + j], v[j]);
    }
    atomicAdd(&g_deg[d], 1);
    #pragma unroll
    for (int h = 0; h < 8; h++) {
        float s = 0.f;
        #pragma unroll
        for (int dd = 0; dd < 8; dd++) s += v[dd] * g_M1[dd * 8 + h];
        g_aedge1[(size_t)e * 8 + h] = s;
    }
    float s2 = 0.f;
    #pragma unroll
    for (int dd = 0; dd < 8; dd++) s2 += v[dd] * g_M2[dd];
    g_aedge2[e] = s2;
}

// ---------------- K2a: single-block exclusive scan of deg -> rowoff --------
__global__ void k_scan() {
    __shared__ int partial[1024];
    int t = threadIdx.x;
    const int CH = (Nn + 1023) / 1024;            // 20
    int s = t * CH;
    int e = min(s + CH, Nn);
    int local = 0;
    for (int i = s; i < e; i++) local += g_deg[i];
    partial[t] = local;
    __syncthreads();
    for (int off = 1; off < 1024; off <<= 1) {
        int v = 0;
        if (t >= off) v = partial[t - off];
        __syncthreads();
        if (t >= off) partial[t] += v;
        __syncthreads();
    }
    int run = (t > 0) ? partial[t - 1] : 0;
    for (int i = s; i < e; i++) {
        g_rowoff[i] = run;
        g_cursor[i] = run;
        run += g_deg[i];
    }
    if (t == 1023) g_rowoff[Nn] = partial[1023];
}

// ---------------- K2b: e_mean -> self-loop attention terms -----------------
__global__ void k_mean() {
    int n = blockIdx.x * blockDim.x + threadIdx.x;
    if (n >= Nn) return;
    float inv = 1.f / fmaxf((float)g_deg[n], 1.f);
    float em[8];
    #pragma unroll
    for (int d = 0; d < 8; d++) em[d] = g_esum[(size_t)n * 8 + d] * inv;
    #pragma unroll
    for (int h = 0; h < 8; h++) {
        float s = 0.f;
        #pragma unroll
        for (int d = 0; d < 8; d++) s += em[d] * g_M1[d * 8 + h];
        g_aloop1[(size_t)n * 8 + h] = s;
    }
    float s2 = 0.f;
    #pragma unroll
    for (int d = 0; d < 8; d++) s2 += em[d] * g_M2[d];
    g_aloop2[n] = s2;
}

// ---------------- K3: CSR fill ----------------
__global__ void k_fill(const int* __restrict__ ei) {
    int e = blockIdx.x * blockDim.x + threadIdx.x;
    if (e >= Ee) return;
    int d = ei[Ee + e];
    int pos = atomicAdd(&g_cursor[d], 1);
    g_csr_src[pos] = ei[e];
    #pragma unroll
    for (int h = 0; h < 8; h++)
        g_csr_ae1[(size_t)h * Ee + pos] = g_aedge1[(size_t)e * 8 + h];
    g_csr_ae2[pos] = g_aedge2[e];
}

// ---------------- K4: GEMM1 h1 = x @ W1 (20000x256 @ 256x256) --------------
#define BM 64
#define BN 64
#define BK 16
__global__ void k_gemm1(const float* __restrict__ X, const float* __restrict__ W) {
    __shared__ float As[BK][BM + 1];
    __shared__ float Bs[BK][BN];
    int tid = threadIdx.x;                 // 256 threads = 16x16
    int tx = tid % 16, ty = tid / 16;
    int brow = blockIdx.x * BM;
    int bcol = blockIdx.y * BN;
    float acc[4][4];
    #pragma unroll
    for (int i = 0; i < 4; i++)
        #pragma unroll
        for (int j = 0; j < 4; j++) acc[i][j] = 0.f;

    for (int k0 = 0; k0 < 256; k0 += BK) {
        #pragma unroll
        for (int i = tid; i < BM * BK; i += 256) {
            int r = i / BK, c = i % BK;
            int gr = brow + r;
            As[c][r] = (gr < Nn) ? X[(size_t)gr * 256 + k0 + c] : 0.f;
        }
        #pragma unroll
        for (int i = tid; i < BK * BN; i += 256) {
            int r = i / BN, c = i % BN;
            Bs[r][c] = W[(size_t)(k0 + r) * 256 + bcol + c];
        }
        __syncthreads();
        #pragma unroll
        for (int kk = 0; kk < BK; kk++) {
            float a[4], b[4];
            #pragma unroll
            for (int i = 0; i < 4; i++) a[i] = As[kk][ty * 4 + i];
            #pragma unroll
            for (int j = 0; j < 4; j++) b[j] = Bs[kk][tx * 4 + j];
            #pragma unroll
            for (int i = 0; i < 4; i++)
                #pragma unroll
                for (int j = 0; j < 4; j++) acc[i][j] += a[i] * b[j];
        }
        __syncthreads();
    }
    #pragma unroll
    for (int i = 0; i < 4; i++) {
        int gr = brow + ty * 4 + i;
        if (gr < Nn) {
            #pragma unroll
            for (int j = 0; j < 4; j++)
                g_h1[(size_t)gr * 256 + bcol + tx * 4 + j] = acc[i][j];
        }
    }
}

// ---------------- K5: per-node attention scalars for conv1 -----------------
__global__ void k_attn1(const float* __restrict__ as1, const float* __restrict__ ad1) {
    int warp = threadIdx.x / 32, lane = threadIdx.x % 32;
    int n = blockIdx.x * 8 + warp;
    if (n >= Nn) return;
    #pragma unroll
    for (int h = 0; h < 8; h++) {
        float val = g_h1[(size_t)n * 256 + h * 32 + lane];
        float s = wredSum(val * __ldg(&as1[h * 32 + lane]));
        float d = wredSum(val * __ldg(&ad1[h * 32 + lane]));
        if (lane == 0) { g_asrc1[(size_t)n * 8 + h] = s; g_adst1[(size_t)n * 8 + h] = d; }
    }
}

// ---------------- K6: conv1 softmax + aggregate (1 block/node, warp/head) --
__global__ void k_conv1(const float* __restrict__ b1) {
    int n = blockIdx.x;
    int h = threadIdx.x / 32, lane = threadIdx.x % 32;
    int beg = g_rowoff[n], end = g_rowoff[n + 1];
    float adst = g_adst1[(size_t)n * 8 + h];
    float self_raw = lrelu(g_asrc1[(size_t)n * 8 + h] + adst + g_aloop1[(size_t)n * 8 + h]);
    const float* ae = g_csr_ae1 + (size_t)h * Ee;

    float m = self_raw;
    for (int j = beg + lane; j < end; j += 32) {
        int s = g_csr_src[j];
        m = fmaxf(m, lrelu(g_asrc1[(size_t)s * 8 + h] + adst + ae[j]));
    }
    m = wredMax(m);

    float ssum = 0.f;
    for (int j = beg + lane; j < end; j += 32) {
        int s = g_csr_src[j];
        ssum += expf(lrelu(g_asrc1[(size_t)s * 8 + h] + adst + ae[j]) - m);
    }
    ssum = wredSum(ssum) + expf(self_raw - m);
    float inv = 1.f / (ssum + 1e-16f);

    float acc = expf(self_raw - m) * inv * g_h1[(size_t)n * 256 + h * 32 + lane];
    for (int base = beg; base < end; base += 32) {
        int j = base + lane;
        float al = 0.f; int s = 0;
        if (j < end) {
            s = g_csr_src[j];
            al = expf(lrelu(g_asrc1[(size_t)s * 8 + h] + adst + ae[j]) - m) * inv;
        }
        int cnt = min(32, end - base);
        for (int i = 0; i < cnt; i++) {
            float a = __shfl_sync(0xffffffffu, al, i);
            int ss = __shfl_sync(0xffffffffu, s, i);
            acc += a * g_h1[(size_t)ss * 256 + h * 32 + lane];
        }
    }
    float v = acc + __ldg(&b1[h * 32 + lane]);
    g_hmid[(size_t)n * 256 + h * 32 + lane] = fmaxf(v, 0.f);   // bias + relu
}

// ---------------- K7: GEMM2 h2 = hmid @ W2 + fused attn scalars ------------
__global__ void k_gemm2(const float* __restrict__ W2, const float* __restrict__ as2,
                        const float* __restrict__ ad2) {
    __shared__ float Ws[256 * 32];
    __shared__ float Xs[8 * 256];
    int tid = threadIdx.x;
    for (int i = tid; i < 256 * 32; i += 256) Ws[i] = W2[i];
    int row0 = blockIdx.x * 8;
    for (int i = tid; i < 8 * 256; i += 256) {
        int r = row0 + i / 256;
        Xs[i] = (r < Nn) ? g_hmid[(size_t)r * 256 + (i % 256)] : 0.f;
    }
    __syncthreads();
    int r = tid / 32, c = tid % 32;
    int n = row0 + r;
    float acc = 0.f;
    #pragma unroll 8
    for (int k = 0; k < 256; k++) acc += Xs[r * 256 + k] * Ws[k * 32 + c];
    if (n < Nn) {
        g_h2[(size_t)n * 32 + c] = acc;
        float s1 = wredSum(acc * __ldg(&as2[c]));
        float s2 = wredSum(acc * __ldg(&ad2[c]));
        if (c == 0) { g_asrc2[n] = s1; g_adst2[n] = s2; }
    }
}

// ---------------- K8: conv2 softmax + aggregate (warp per node) ------------
__global__ void k_conv2(const float* __restrict__ b2, float* __restrict__ out) {
    int warp = threadIdx.x / 32, lane = threadIdx.x % 32;
    int n = blockIdx.x * 8 + warp;
    if (n >= Nn) return;
    int beg = g_rowoff[n], end = g_rowoff[n + 1];
    float adst = g_adst2[n];
    float self_raw = lrelu(g_asrc2[n] + adst + g_aloop2[n]);

    float m = self_raw;
    for (int j = beg + lane; j < end; j += 32)
        m = fmaxf(m, lrelu(g_asrc2[g_csr_src[j]] + adst + g_csr_ae2[j]));
    m = wredMax(m);

    float ssum = 0.f;
    for (int j = beg + lane; j < end; j += 32)
        ssum += expf(lrelu(g_asrc2[g_csr_src[j]] + adst + g_csr_ae2[j]) - m);
    ssum = wredSum(ssum) + expf(self_raw - m);
    float inv = 1.f / (ssum + 1e-16f);

    float acc = expf(self_raw - m) * inv * g_h2[(size_t)n * 32 + lane];
    for (int base = beg; base < end; base += 32) {
        int j = base + lane;
        float al = 0.f; int s = 0;
        if (j < end) {
            s = g_csr_src[j];
            al = expf(lrelu(g_asrc2[s] + adst + g_csr_ae2[j]) - m) * inv;
        }
        int cnt = min(32, end - base);
        for (int i = 0; i < cnt; i++) {
            float a = __shfl_sync(0xffffffffu, al, i);
            int ss = __shfl_sync(0xffffffffu, s, i);
            acc += a * g_h2[(size_t)ss * 32 + lane];
        }
    }
    out[(size_t)n * 32 + lane] = acc + __ldg(&b2[lane]);
}

// ---------------- launcher ----------------
extern "C" void kernel_launch(void* const* d_in, const int* in_sizes, int n_in,
                              void* d_out, int out_size) {
    const float* x   = (const float*)d_in[0];
    const int*   ei  = (const int*)  d_in[1];
    const float* ea  = (const float*)d_in[2];
    const float* Wse = (const float*)d_in[3];
    const float* bse = (const float*)d_in[4];
    const float* W1  = (const float*)d_in[5];
    const float* as1 = (const float*)d_in[6];
    const float* ad1 = (const float*)d_in[7];
    const float* We1 = (const float*)d_in[8];
    const float* ae1 = (const float*)d_in[9];
    const float* b1  = (const float*)d_in[10];
    const float* W2  = (const float*)d_in[11];
    const float* as2 = (const float*)d_in[12];
    const float* ad2 = (const float*)d_in[13];
    const float* We2 = (const float*)d_in[14];
    const float* ae2 = (const float*)d_in[15];
    const float* b2  = (const float*)d_in[16];
    float* out = (float*)d_out;

    k_init<<<(Nn * EDIM + 255) / 256, 256>>>();
    k_pre<<<1, 64>>>(We1, ae1, We2, ae2);
    k_edge<<<(Ee + 255) / 256, 256>>>(ei, ea, Wse, bse);
    k_scan<<<1, 1024>>>();
    k_mean<<<(Nn + 255) / 256, 256>>>();
    k_fill<<<(Ee + 255) / 256, 256>>>(ei);
    dim3 g1((Nn + BM - 1) / BM, 256 / BN);
    k_gemm1<<<g1, 256>>>(x, W1);
    k_attn1<<<(Nn + 7) / 8, 256>>>(as1, ad1);
    k_conv1<<<Nn, 256>>>(b1);
    k_gemm2<<<(Nn + 7) / 8, 256>>>(W2, as2, ad2);
    k_conv2<<<(Nn + 7) / 8, 256>>>(b2, out);
}